// round 12
// baseline (speedup 1.0000x reference)
#include <cuda_runtime.h>
#include <cuda_bf16.h>
#include <cuda_fp16.h>
#include <stdint.h>
#include <math.h>

// ---------------------------------------------------------------------------
// Problem constants
// ---------------------------------------------------------------------------
#define NUM_CLASSES 10
#define DD     64
#define MAXB   1024
#define NE_PAD 50048           // 391 tiles of 128
#define GAMMA  1.0f
#define EPS    1e-12f

// Hybrid tiling: per 128x128 tile, cols 0-95 via bf16 HMMA (f32 acc),
// cols 96-127 via f16 HFMA2 SIMT on the fma pipe.
#define TM 128
#define TN 128
#define TNT 96                 // tensor columns
#define GCOLS 37               // grid = 8 x 37 = 296 CTAs = 2/SM, one wave
#define ROWB 144               // smem row stride (64 x 2B + 16 pad)

#define SM_ABF 0                       // A tile, bf16 (MMA)
#define SM_AF  18432                   // A tile, f16  (SIMT)
#define SM_B0  36864                   // B tile buf 0 (mixed dtype by col)
#define SM_E20 55296                   // e2 stage buf 0 (512B)
#define SM_B1  55808
#define SM_E21 74240
#define SM_TOT 74752

#define MAXSURV (1u * 1024u * 1024u)

// ---------------------------------------------------------------------------
// Scratch (__device__ globals; no cudaMalloc allowed). Zero-init; the kernel
// tail self-resets counters so graph replays are deterministic.
// ---------------------------------------------------------------------------
__device__ uint16_t g_e16[(size_t)NE_PAD * DD];  // (r%128)<96: bf16, else f16
__device__ uint16_t g_xbf[(size_t)MAXB * DD];    // x as bf16
__device__ uint16_t g_xf [(size_t)MAXB * DD];    // x as f16
__device__ float g_e2[NE_PAD];
__device__ float g_x2[MAXB];
__device__ float g_class[MAXB * NUM_CLASSES];
__device__ float g_beta;
__device__ unsigned g_nsurv, g_done, g_bar1, g_bar2;
__device__ unsigned g_surv[MAXSURV];

// ---------------------------------------------------------------------------
// PTX helpers (baseline ISA only)
// ---------------------------------------------------------------------------
__device__ __forceinline__ uint32_t smem_to_u32(const void* p) {
    uint32_t a;
    asm("{ .reg .u64 t; cvta.to.shared.u64 t, %1; cvt.u32.u64 %0, t; }"
        : "=r"(a) : "l"(p));
    return a;
}
__device__ __forceinline__ void ldsm_x4(uint32_t* r, uint32_t addr) {
    asm volatile("ldmatrix.sync.aligned.m8n8.x4.shared.b16 {%0,%1,%2,%3}, [%4];"
                 : "=r"(r[0]), "=r"(r[1]), "=r"(r[2]), "=r"(r[3]) : "r"(addr));
}
__device__ __forceinline__ void ldsm_x2(uint32_t* r, uint32_t addr) {
    asm volatile("ldmatrix.sync.aligned.m8n8.x2.shared.b16 {%0,%1}, [%2];"
                 : "=r"(r[0]), "=r"(r[1]) : "r"(addr));
}
__device__ __forceinline__ void mma_bf16(float* c, const uint32_t* a,
                                         const uint32_t* b) {
    asm volatile(
        "mma.sync.aligned.m16n8k16.row.col.f32.bf16.bf16.f32 "
        "{%0,%1,%2,%3}, {%4,%5,%6,%7}, {%8,%9}, {%0,%1,%2,%3};"
        : "+f"(c[0]), "+f"(c[1]), "+f"(c[2]), "+f"(c[3])
        : "r"(a[0]), "r"(a[1]), "r"(a[2]), "r"(a[3]), "r"(b[0]), "r"(b[1]));
}
__device__ __forceinline__ void cp_async16(uint32_t dst, const void* src) {
    asm volatile("cp.async.cg.shared.global [%0], [%1], 16;"
                 :: "r"(dst), "l"(src) : "memory");
}
__device__ __forceinline__ void cp_async4(uint32_t dst, const void* src) {
    asm volatile("cp.async.ca.shared.global [%0], [%1], 4;"
                 :: "r"(dst), "l"(src) : "memory");
}
__device__ __forceinline__ void cp_commit() {
    asm volatile("cp.async.commit_group;" ::: "memory");
}
template <int N>
__device__ __forceinline__ void cp_wait() {
    asm volatile("cp.async.wait_group %0;" :: "n"(N) : "memory");
}
__device__ __forceinline__ unsigned ld_cg_u32(const unsigned* p) {
    unsigned v;
    asm volatile("ld.global.cg.u32 %0, [%1];" : "=r"(v) : "l"(p));
    return v;
}
__device__ __forceinline__ void push_surv(int row, int col) {
    unsigned q = atomicAdd(&g_nsurv, 1u);
    if (q < MAXSURV) g_surv[q] = ((unsigned)row << 16) | (unsigned)col;
}

// ---------------------------------------------------------------------------
// Fused kernel: prep -> grid barrier -> hybrid filter GEMM -> grid barrier ->
// exact survivor recompute -> last-block finalize (+ counter reset).
// Grid = RT*GCOLS = 296 CTAs = exactly 2/SM resident (spin barriers are safe).
// ---------------------------------------------------------------------------
__global__ void __launch_bounds__(256, 2)
fused_kernel(const float* __restrict__ x, const float* __restrict__ ex,
             const int* __restrict__ labels, const float* __restrict__ beta_raw,
             float* __restrict__ out, int B, int NE, int nout) {
    extern __shared__ char smem[];
    const int t = threadIdx.x;
    const unsigned gid = blockIdx.x * 256u + t;
    const unsigned nthr = gridDim.x * 256u;

    // ================= Phase 0: prep (grid-strided) =================
    for (unsigned i = gid; i < MAXB * NUM_CLASSES; i += nthr) g_class[i] = 0.f;
    if (gid == 0) {
        float br = beta_raw[0];
        g_beta = (br > 20.f) ? br : log1pf(expf(br));
    }
    // 8 threads per row, 8 floats each. nthr % 8 == 0 keeps (task&7)==(t&7).
    const unsigned ntask = (NE_PAD + MAXB) * 8u;
    for (unsigned task = gid; task < ntask; task += nthr) {
        const int R = task >> 3;
        const int part = task & 7;
        bool is_x = false;
        int outr = R;
        const float* src = nullptr;
        if (R < NE_PAD) {
            if (R < NE) src = ex + (size_t)R * DD + part * 8;
        } else {
            int xr = R - NE_PAD;
            is_x = true; outr = xr;
            if (xr < B) src = x + (size_t)xr * DD + part * 8;
        }
        float v[8];
        float s = 0.f;
        if (src) {
            #pragma unroll
            for (int q = 0; q < 2; q++) {
                float4 f = ((const float4*)src)[q];
                v[4*q+0] = f.x; v[4*q+1] = f.y; v[4*q+2] = f.z; v[4*q+3] = f.w;
                s += f.x*f.x + f.y*f.y + f.z*f.z + f.w*f.w;
            }
        } else {
            #pragma unroll
            for (int q = 0; q < 8; q++) v[q] = 0.f;
        }
        #pragma unroll
        for (int d = 1; d <= 4; d <<= 1)
            s += __shfl_xor_sync(0xFFFFFFFFu, s, d);
        if (is_x) {
            alignas(16) uint16_t hb[8], hf[8];
            #pragma unroll
            for (int q = 0; q < 8; q++) {
                __nv_bfloat16 b16 = __float2bfloat16(v[q]);
                __half h16 = __float2half_rn(v[q]);
                hb[q] = *(uint16_t*)&b16;
                hf[q] = *(uint16_t*)&h16;
            }
            *(uint4*)(g_xbf + (size_t)outr * DD + part * 8) = *(uint4*)hb;
            *(uint4*)(g_xf  + (size_t)outr * DD + part * 8) = *(uint4*)hf;
            if (part == 0) g_x2[outr] = (outr < B) ? s : 0.f;
        } else {
            const bool use_bf = ((R & 127) < TNT);   // col region in its tile
            alignas(16) uint16_t hh[8];
            #pragma unroll
            for (int q = 0; q < 8; q++) {
                if (use_bf) {
                    __nv_bfloat16 b16 = __float2bfloat16(v[q]);
                    hh[q] = *(uint16_t*)&b16;
                } else {
                    __half h16 = __float2half_rn(v[q]);
                    hh[q] = *(uint16_t*)&h16;
                }
            }
            *(uint4*)(g_e16 + (size_t)outr * DD + part * 8) = *(uint4*)hh;
            if (part == 0) g_e2[outr] = (outr < NE) ? s : 3.0e8f;
        }
    }

    // ---- grid barrier 1 ----
    __threadfence();
    __syncthreads();
    if (t == 0) {
        atomicAdd(&g_bar1, 1u);
        while (ld_cg_u32(&g_bar1) < gridDim.x) __nanosleep(128);
    }
    __syncthreads();
    __threadfence();

    // ================= Phase 1: hybrid filter GEMM =================
    const int RT = (B + TM - 1) / TM;
    const int rb = blockIdx.x % RT;
    const int cg = blockIdx.x / RT;
    const int bm = rb * TM;
    const int NT = (NE + TN - 1) / TN;
    const int wid = t >> 5, lane = t & 31;

    const uint32_t sAbf = smem_to_u32(smem) + SM_ABF;
    const uint32_t sAf  = smem_to_u32(smem) + SM_AF;
    const uint32_t sB_[2]  = { smem_to_u32(smem) + SM_B0, smem_to_u32(smem) + SM_B1 };
    const uint32_t sE2_[2] = { smem_to_u32(smem) + SM_E20, smem_to_u32(smem) + SM_E21 };

    // A tiles (bf16 + f16), 128 rows x 128B each.
    for (int i = t; i < TM * 8; i += 256) {
        int r = i >> 3, c = i & 7;
        *(uint4*)(smem + SM_ABF + r * ROWB + c * 16) =
            *(const uint4*)(g_xbf + (size_t)(bm + r) * DD + c * 8);
        *(uint4*)(smem + SM_AF + r * ROWB + c * 16) =
            *(const uint4*)(g_xf + (size_t)(bm + r) * DD + c * 8);
    }

    // --- MMA config: 2x4 warp grid over 128 x 96, warp-tile 64x24 ---
    const int warpM = wid >> 2, warpN = wid & 3;
    const int rowA = (lane & 7) + ((lane >> 3) & 1) * 8;
    const int kA   = ((lane >> 4) & 1) * 8;
    const int l16  = lane & 15;
    const int rowBf = l16 & 7;
    const int kB    = ((l16 >> 3) & 1) * 8;
    uint32_t aAddr[4];
    #pragma unroll
    for (int mi = 0; mi < 4; mi++)
        aAddr[mi] = sAbf + (uint32_t)(warpM * 64 + mi * 16 + rowA) * ROWB + kA * 2;
    uint32_t bOff[3];
    #pragma unroll
    for (int ni = 0; ni < 3; ni++)
        bOff[ni] = (uint32_t)(warpN * 24 + ni * 8 + rowBf) * ROWB + kB * 2;

    const float beta = g_beta;
    const float thr_t = 60.f / beta + 2.0f;   // bf16+f32acc margin
    const float thr_s = 60.f / beta + 5.0f;   // f16+f16acc margin

    float x2a[4], x2b[4];
    #pragma unroll
    for (int mi = 0; mi < 4; mi++) {
        int r0 = bm + warpM * 64 + mi * 16 + (lane >> 2);
        x2a[mi] = g_x2[r0];
        x2b[mi] = g_x2[r0 + 8];
    }
    float xmin8 = fminf(fminf(fminf(x2a[0], x2b[0]), fminf(x2a[1], x2b[1])),
                        fminf(fminf(x2a[2], x2b[2]), fminf(x2a[3], x2b[3])));

    // --- SIMT config: warp covers rows wid*16..+15, cols 96..127 ---
    const int srg = lane >> 3;        // 0..3
    const int scg = lane & 7;         // 0..7
    const int srow0 = wid * 16 + srg; // + 4*rr
    uint32_t sArd = sAf + (uint32_t)srow0 * ROWB;          // + 4*rr*ROWB + k4*8
    float sx2[4];
    #pragma unroll
    for (int rr = 0; rr < 4; rr++) sx2[rr] = g_x2[bm + srow0 + 4 * rr];

    // loader: 2 threads/row, 4x16B each + e2 stage (t<128)
    const int pr = t >> 1;
    const int pc = (t & 1) * 2;
    auto issue_b = [&](int buf, int bn) {
        const uint16_t* src = g_e16 + (size_t)(bn + pr) * DD;
        uint32_t drow = sB_[buf] + (uint32_t)pr * ROWB;
        cp_async16(drow + (pc + 0) * 16, src + (pc + 0) * 8);
        cp_async16(drow + (pc + 1) * 16, src + (pc + 1) * 8);
        cp_async16(drow + (pc + 4) * 16, src + (pc + 4) * 8);
        cp_async16(drow + (pc + 5) * 16, src + (pc + 5) * 8);
        if (t < 128) cp_async4(sE2_[buf] + t * 4, g_e2 + bn + t);
    };

    issue_b(0, cg * TN);
    cp_commit();

    const int stagger = (warpM ^ (blockIdx.x & 1)) & 1;

    int it = 0;
    for (int et = cg; et < NT; et += GCOLS, it++) {
        const int bn = et * TN;
        const int buf = it & 1;
        const uint32_t curB = sB_[buf];
        const uint32_t curE = sE2_[buf];
        const int etn = et + GCOLS;
        if (etn < NT) {
            issue_b(buf ^ 1, etn * TN);
            cp_commit();
            cp_wait<1>();
        } else {
            cp_wait<0>();
        }
        __syncthreads();

        // ---------------- MMA slice (cols bn .. bn+95) ----------------
        auto do_mma = [&]() {
            float2 e2p[3];
            #pragma unroll
            for (int ni = 0; ni < 3; ni++) {
                uint32_t ea = curE + (warpN * 24 + ni * 8 + 2 * (lane & 3)) * 4;
                asm volatile("ld.shared.v2.f32 {%0,%1}, [%2];"
                             : "=f"(e2p[ni].x), "=f"(e2p[ni].y) : "r"(ea));
            }
            float acc[4][3][4];
            #pragma unroll
            for (int mi = 0; mi < 4; mi++)
                #pragma unroll
                for (int ni = 0; ni < 3; ni++)
                    #pragma unroll
                    for (int r = 0; r < 4; r++) acc[mi][ni][r] = 0.f;
            #pragma unroll
            for (int ks = 0; ks < 4; ks++) {
                const int k0b = ks * 32;
                uint32_t af[4][4];
                #pragma unroll
                for (int mi = 0; mi < 4; mi++) ldsm_x4(af[mi], aAddr[mi] + k0b);
                uint32_t bf[3][2];
                #pragma unroll
                for (int ni = 0; ni < 3; ni++) ldsm_x2(bf[ni], curB + bOff[ni] + k0b);
                #pragma unroll
                for (int mi = 0; mi < 4; mi++)
                    #pragma unroll
                    for (int ni = 0; ni < 3; ni++)
                        mma_bf16(acc[mi][ni], af[mi], bf[ni]);
            }
            // hierarchical gate per ni: max over 16 accs
            #pragma unroll
            for (int ni = 0; ni < 3; ni++) {
                float mx = acc[0][ni][0];
                #pragma unroll
                for (int mi = 0; mi < 4; mi++)
                    #pragma unroll
                    for (int r = 0; r < 4; r++) mx = fmaxf(mx, acc[mi][ni][r]);
                float e2mn = fminf(e2p[ni].x, e2p[ni].y);
                if (xmin8 + e2mn - 2.f * mx < thr_t) {
                    #pragma unroll
                    for (int mi = 0; mi < 4; mi++)
                        #pragma unroll
                        for (int r = 0; r < 4; r++) {
                            float x2v = (r >= 2) ? x2b[mi] : x2a[mi];
                            float e2v = (r & 1) ? e2p[ni].y : e2p[ni].x;
                            if (x2v + e2v - 2.f * acc[mi][ni][r] < thr_t) {
                                int row = bm + warpM * 64 + mi * 16 +
                                          (lane >> 2) + ((r >> 1) << 3);
                                int col = bn + warpN * 24 + ni * 8 +
                                          2 * (lane & 3) + (r & 1);
                                push_surv(row, col);
                            }
                        }
                }
            }
        };

        // ---------------- SIMT slice (cols bn+96 .. bn+127) ----------------
        auto do_simt = [&]() {
            float e2c[4];
            #pragma unroll
            for (int cc = 0; cc < 4; cc++) {
                uint32_t ea = curE + (TNT + scg + 8 * cc) * 4;
                asm volatile("ld.shared.f32 %0, [%1];" : "=f"(e2c[cc]) : "r"(ea));
            }
            float e2mn = fminf(fminf(e2c[0], e2c[1]), fminf(e2c[2], e2c[3]));
            __half2 acc[4][4];
            #pragma unroll
            for (int rr = 0; rr < 4; rr++)
                #pragma unroll
                for (int cc = 0; cc < 4; cc++)
                    acc[rr][cc] = __half2half2(__ushort_as_half(0));
            uint32_t bBase = curB + (uint32_t)(TNT + scg) * ROWB;
            #pragma unroll
            for (int k4 = 0; k4 < 16; k4++) {
                __half2 av[4][2], bv[4][2];
                #pragma unroll
                for (int rr = 0; rr < 4; rr++) {
                    uint2 u;
                    asm volatile("ld.shared.v2.u32 {%0,%1}, [%2];"
                        : "=r"(u.x), "=r"(u.y)
                        : "r"(sArd + (uint32_t)(4 * rr) * ROWB + k4 * 8));
                    av[rr][0] = *(__half2*)&u.x; av[rr][1] = *(__half2*)&u.y;
                }
                #pragma unroll
                for (int cc = 0; cc < 4; cc++) {
                    uint2 u;
                    asm volatile("ld.shared.v2.u32 {%0,%1}, [%2];"
                        : "=r"(u.x), "=r"(u.y)
                        : "r"(bBase + (uint32_t)(8 * cc) * ROWB + k4 * 8));
                    bv[cc][0] = *(__half2*)&u.x; bv[cc][1] = *(__half2*)&u.y;
                }
                #pragma unroll
                for (int rr = 0; rr < 4; rr++)
                    #pragma unroll
                    for (int cc = 0; cc < 4; cc++) {
                        acc[rr][cc] = __hfma2(av[rr][0], bv[cc][0], acc[rr][cc]);
                        acc[rr][cc] = __hfma2(av[rr][1], bv[cc][1], acc[rr][cc]);
                    }
            }
            #pragma unroll
            for (int rr = 0; rr < 4; rr++) {
                __half2 f0 = __hadd2(acc[rr][0], __lowhigh2highlow(acc[rr][0]));
                __half2 f1 = __hadd2(acc[rr][1], __lowhigh2highlow(acc[rr][1]));
                __half2 f2 = __hadd2(acc[rr][2], __lowhigh2highlow(acc[rr][2]));
                __half2 f3 = __hadd2(acc[rr][3], __lowhigh2highlow(acc[rr][3]));
                __half2 mm = __hmax2(__hmax2(f0, f1), __hmax2(f2, f3));
                float mx = __low2float(mm);
                if (sx2[rr] + e2mn - 2.f * mx < thr_s) {
                    #pragma unroll
                    for (int cc = 0; cc < 4; cc++) {
                        float2 d = __half22float2(acc[rr][cc]);
                        float dot = d.x + d.y;
                        if (sx2[rr] + e2c[cc] - 2.f * dot < thr_s) {
                            int row = bm + srow0 + 4 * rr;
                            int col = bn + TNT + scg + 8 * cc;
                            push_surv(row, col);
                        }
                    }
                }
            }
        };

        if (stagger) { do_simt(); do_mma(); }
        else         { do_mma();  do_simt(); }
        __syncthreads();
    }

    // ---- grid barrier 2 (all survivor pushes visible) ----
    __threadfence();
    __syncthreads();
    if (t == 0) {
        atomicAdd(&g_bar2, 1u);
        while (ld_cg_u32(&g_bar2) < gridDim.x) __nanosleep(128);
    }
    __syncthreads();
    __threadfence();

    // ================= Phase 2: exact survivor recompute =================
    {
        unsigned n = ld_cg_u32(&g_nsurv);
        if (n > MAXSURV) n = MAXSURV;
        for (unsigned i = gid; i < n; i += nthr) {
            unsigned p = g_surv[i];
            int row = (int)(p >> 16);
            int col = (int)(p & 0xFFFFu);
            if (row >= B || col >= NE) continue;
            const float* xr = x  + (size_t)row * DD;
            const float* er = ex + (size_t)col * DD;
            float s = 0.f;
            #pragma unroll
            for (int q = 0; q < DD / 4; q++) {
                float4 a = ((const float4*)xr)[q];
                float4 e = ((const float4*)er)[q];
                s += a.x*e.x + a.y*e.y + a.z*e.z + a.w*e.w;
            }
            float d2 = fmaxf(g_x2[row] + g_e2[col] - 2.f * s, 0.f);
            float bd = beta * d2;
            // skipped mass <= NE*exp(-60) << 1e-3 * EPS
            if (bd < 60.f)
                atomicAdd(&g_class[row * NUM_CLASSES + labels[col]], expf(-bd));
        }
    }

    // ================= Phase 3: finalize (last block) =================
    __shared__ unsigned s_last;
    __threadfence();
    __syncthreads();
    if (t == 0)
        s_last = (atomicAdd(&g_done, 1u) == gridDim.x - 1) ? 1u : 0u;
    __syncthreads();
    if (s_last) {
        __threadfence();
        for (int i = t; i < nout; i += 256)
            out[i] = GAMMA * logf(g_class[i] + EPS);
        __syncthreads();
        if (t == 0) {   // reset for next graph replay
            g_nsurv = 0u; g_done = 0u; g_bar1 = 0u; g_bar2 = 0u;
            __threadfence();
        }
    }
}

// ---------------------------------------------------------------------------
extern "C" void kernel_launch(void* const* d_in, const int* in_sizes, int n_in,
                              void* d_out, int out_size) {
    const float* x        = (const float*)d_in[0];
    const float* ex       = (const float*)d_in[1];
    const int*   labels   = (const int*)d_in[2];
    const float* beta_raw = (const float*)d_in[3];
    float* out = (float*)d_out;

    const int B  = in_sizes[0] / DD;
    const int NE = in_sizes[1] / DD;

    cudaFuncSetAttribute(fused_kernel,
                         cudaFuncAttributeMaxDynamicSharedMemorySize, SM_TOT);
    const int RT = (B + TM - 1) / TM;
    fused_kernel<<<RT * GCOLS, 256, SM_TOT>>>(x, ex, labels, beta_raw, out,
                                              B, NE, out_size);
}

// round 13
// speedup vs baseline: 1.3769x; 1.3769x over previous
#include <cuda_runtime.h>
#include <cuda_bf16.h>
#include <stdint.h>
#include <math.h>

// ---------------------------------------------------------------------------
// Problem constants
// ---------------------------------------------------------------------------
#define NUM_CLASSES 10
#define DD     64
#define MAXB   1024
#define NE_PAD 50048           // 782 tiles of 64
#define GAMMA  1.0f
#define EPS    1e-12f

// Tiling: bf16 HMMA (f32 acc) filter GEMM, occupancy-first.
// CTA tile 128(M) x 64(N); warp grid 4(M) x 2(N); warp tile 32x32.
#define TM 128
#define TN 64
#define GCOLS 74               // grid = 8 x 74 = 592 CTAs = 4/SM, one wave
#define ROWB 144               // smem row stride (64 x 2B + 16 pad)

#define MAXSURV (1u * 1024u * 1024u)

// ---------------------------------------------------------------------------
// Scratch (__device__ globals; no cudaMalloc allowed)
// ---------------------------------------------------------------------------
__device__ __nv_bfloat16 g_eh[(size_t)NE_PAD * DD];
__device__ __nv_bfloat16 g_xh[(size_t)MAXB * DD];
__device__ float g_e2[NE_PAD];
__device__ float g_x2[MAXB];
__device__ float g_class[MAXB * NUM_CLASSES];
__device__ float g_beta;
__device__ unsigned g_nsurv, g_done;
__device__ unsigned g_surv[MAXSURV];

// ---------------------------------------------------------------------------
// PTX helpers (baseline ISA only)
// ---------------------------------------------------------------------------
__device__ __forceinline__ uint32_t smem_to_u32(const void* p) {
    uint32_t a;
    asm("{ .reg .u64 t; cvta.to.shared.u64 t, %1; cvt.u32.u64 %0, t; }"
        : "=r"(a) : "l"(p));
    return a;
}
__device__ __forceinline__ void ldsm_x4(uint32_t* r, uint32_t addr) {
    asm volatile("ldmatrix.sync.aligned.m8n8.x4.shared.b16 {%0,%1,%2,%3}, [%4];"
                 : "=r"(r[0]), "=r"(r[1]), "=r"(r[2]), "=r"(r[3]) : "r"(addr));
}
__device__ __forceinline__ void mma_bf16(float* c, const uint32_t* a,
                                         const uint32_t* b) {
    asm volatile(
        "mma.sync.aligned.m16n8k16.row.col.f32.bf16.bf16.f32 "
        "{%0,%1,%2,%3}, {%4,%5,%6,%7}, {%8,%9}, {%0,%1,%2,%3};"
        : "+f"(c[0]), "+f"(c[1]), "+f"(c[2]), "+f"(c[3])
        : "r"(a[0]), "r"(a[1]), "r"(a[2]), "r"(a[3]), "r"(b[0]), "r"(b[1]));
}
__device__ __forceinline__ void cp_async16(uint32_t dst, const void* src) {
    asm volatile("cp.async.cg.shared.global [%0], [%1], 16;"
                 :: "r"(dst), "l"(src) : "memory");
}
__device__ __forceinline__ void cp_commit() {
    asm volatile("cp.async.commit_group;" ::: "memory");
}
template <int N>
__device__ __forceinline__ void cp_wait() {
    asm volatile("cp.async.wait_group %0;" :: "n"(N) : "memory");
}

// ---------------------------------------------------------------------------
// Prep: bf16 conversion (padded), exact L2 norms, beta, zero bins.
// ---------------------------------------------------------------------------
__global__ void prep_kernel(const float* __restrict__ x,
                            const float* __restrict__ ex,
                            const float* __restrict__ beta_raw,
                            int B, int NE) {
    const int t = threadIdx.x;
    const int gid = blockIdx.x * 256 + t;
    if (gid < MAXB * NUM_CLASSES) g_class[gid] = 0.f;
    if (gid == 0) {
        float br = beta_raw[0];
        g_beta = (br > 20.f) ? br : log1pf(expf(br));
        g_nsurv = 0u;
        g_done  = 0u;
    }
    const int R = blockIdx.x * 32 + (t >> 3);   // padded row index
    const int part = t & 7;                      // 8-float segment
    bool is_x = false;
    int outr = R;
    const float* src = nullptr;
    if (R < NE_PAD) {
        if (R < NE) src = ex + (size_t)R * DD + part * 8;
    } else {
        int xr = R - NE_PAD;
        if (xr >= MAXB) return;
        is_x = true; outr = xr;
        if (xr < B) src = x + (size_t)xr * DD + part * 8;
    }
    float v[8];
    float s = 0.f;
    if (src) {
        #pragma unroll
        for (int q = 0; q < 2; q++) {
            float4 f = ((const float4*)src)[q];
            v[4*q+0] = f.x; v[4*q+1] = f.y; v[4*q+2] = f.z; v[4*q+3] = f.w;
            s += f.x*f.x + f.y*f.y + f.z*f.z + f.w*f.w;
        }
    } else {
        #pragma unroll
        for (int q = 0; q < 8; q++) v[q] = 0.f;
    }
    #pragma unroll
    for (int d = 1; d <= 4; d <<= 1)
        s += __shfl_xor_sync(0xFFFFFFFFu, s, d);
    alignas(16) __nv_bfloat16 hb[8];
    #pragma unroll
    for (int q = 0; q < 8; q++) hb[q] = __float2bfloat16(v[q]);
    __nv_bfloat16* dst = (is_x ? (g_xh + (size_t)outr * DD)
                               : (g_eh + (size_t)outr * DD)) + part * 8;
    *(uint4*)dst = *(uint4*)hb;
    if (part == 0) {
        if (is_x) g_x2[outr] = (outr < B) ? s : 0.f;
        else      g_e2[outr] = (outr < NE) ? s : 3.0e8f;  // padding never fires
    }
}

// ---------------------------------------------------------------------------
// Main: bf16 HMMA (f32 acc) filter GEMM, occupancy 4 CTAs/SM (32 warps).
// Warp tile 32x32 (32 acc regs). Hierarchical gate -> rare survivor push.
// Margin 2 >> bf16 dot error (~0.35): every true survivor is kept; survivors
// recomputed exactly in fp32 later => rel_err unchanged.
// ---------------------------------------------------------------------------
__global__ void __launch_bounds__(256, 4)
exemplar_mma_kernel(int B, int NE) {
    __shared__ __align__(16) char sA[TM * ROWB];       // 18432
    __shared__ __align__(16) char sB[2][TN * ROWB];    // 2 x 9216

    const uint32_t saU = smem_to_u32(sA);
    const uint32_t sbU[2] = { smem_to_u32(sB[0]), smem_to_u32(sB[1]) };

    const int t = threadIdx.x;
    const int wid = t >> 5, lane = t & 31;
    const int warpM = wid >> 1;            // 0..3
    const int warpN = wid & 1;             // 0..1
    const int bm = blockIdx.y * TM;
    const int NT = (NE + TN - 1) / TN;

    // Load A tile (128 rows x 64 bf16) once.
    for (int i = t; i < TM * 8; i += 256) {
        int r = i >> 3, c = i & 7;
        *(uint4*)(sA + r * ROWB + c * 16) =
            *(const uint4*)(g_xh + (size_t)(bm + r) * DD + c * 8);
    }

    // ldsm lane addressing.
    // A (x4): mats m0-7/k0-7, m8-15/k0-7, m0-7/k8-15, m8-15/k8-15
    const int rowA = (lane & 7) + ((lane >> 3) & 1) * 8;
    const int kAby = ((lane >> 4) & 1) * 16;
    // B (x4): mats n0-7/k0-7, n0-7/k8-15, n8-15/k0-7, n8-15/k8-15
    //   -> regs {0,1} = frag for n0-7, {2,3} = frag for n8-15
    const int rowB = (lane & 7) + ((lane >> 4) & 1) * 8;
    const int kBby = ((lane >> 3) & 1) * 16;

    uint32_t aAddr[2];
    #pragma unroll
    for (int mi = 0; mi < 2; mi++)
        aAddr[mi] = saU + (uint32_t)(warpM * 32 + mi * 16 + rowA) * ROWB + kAby;
    uint32_t bOff[2];
    #pragma unroll
    for (int nn = 0; nn < 2; nn++)
        bOff[nn] = (uint32_t)(warpN * 32 + nn * 16 + rowB) * ROWB + kBby;

    const float beta = g_beta;
    const float thr  = 60.f / beta + 2.0f;

    // x2 for this thread's 4 rows; xmin for the group bound.
    float x2v[4];
    #pragma unroll
    for (int mi = 0; mi < 2; mi++) {
        int r0 = bm + warpM * 32 + mi * 16 + (lane >> 2);
        x2v[mi * 2 + 0] = g_x2[r0];
        x2v[mi * 2 + 1] = g_x2[r0 + 8];
    }
    const float xmin = fminf(fminf(x2v[0], x2v[1]), fminf(x2v[2], x2v[3]));

    // cp.async B-tile loader: 64 rows x 8 chunks of 16B; 4 threads/row.
    const int pr = t >> 2;
    const int pc = (t & 3) * 2;
    auto issue_b = [&](int buf, int bn) {
        const __nv_bfloat16* src = g_eh + (size_t)(bn + pr) * DD;
        uint32_t drow = sbU[buf] + (uint32_t)pr * ROWB;
        cp_async16(drow + (pc + 0) * 16, src + (pc + 0) * 8);
        cp_async16(drow + (pc + 1) * 16, src + (pc + 1) * 8);
    };

    issue_b(0, blockIdx.x * TN);
    cp_commit();

    int it = 0;
    for (int et = blockIdx.x; et < NT; et += GCOLS, it++) {
        const int bn = et * TN;
        const int buf = it & 1;
        const uint32_t cur = sbU[buf];
        const int etn = et + GCOLS;
        if (etn < NT) {
            issue_b(buf ^ 1, etn * TN);
            cp_commit();
            cp_wait<1>();
        } else {
            cp_wait<0>();
        }
        __syncthreads();

        // e2 for this thread's 8 cols (L1/L2 cached).
        float2 e2p[4];
        #pragma unroll
        for (int ni = 0; ni < 4; ni++)
            e2p[ni] = *(const float2*)&g_e2[bn + warpN * 32 + ni * 8 + 2 * (lane & 3)];

        float acc[2][4][4];
        #pragma unroll
        for (int mi = 0; mi < 2; mi++)
            #pragma unroll
            for (int ni = 0; ni < 4; ni++)
                #pragma unroll
                for (int r = 0; r < 4; r++) acc[mi][ni][r] = 0.f;

        #pragma unroll
        for (int ks = 0; ks < 4; ks++) {
            const int k0b = ks * 32;
            uint32_t af[2][4];
            #pragma unroll
            for (int mi = 0; mi < 2; mi++) ldsm_x4(af[mi], aAddr[mi] + k0b);
            uint32_t bf[2][4];
            #pragma unroll
            for (int nn = 0; nn < 2; nn++) ldsm_x4(bf[nn], cur + bOff[nn] + k0b);
            #pragma unroll
            for (int mi = 0; mi < 2; mi++)
                #pragma unroll
                for (int nn = 0; nn < 2; nn++) {
                    mma_bf16(acc[mi][nn * 2 + 0], af[mi], &bf[nn][0]);
                    mma_bf16(acc[mi][nn * 2 + 1], af[mi], &bf[nn][2]);
                }
        }

        // Hierarchical gate per ni: fmax tree over 8 accs -> rare scan.
        #pragma unroll
        for (int ni = 0; ni < 4; ni++) {
            float mx = acc[0][ni][0];
            #pragma unroll
            for (int mi = 0; mi < 2; mi++)
                #pragma unroll
                for (int r = 0; r < 4; r++) mx = fmaxf(mx, acc[mi][ni][r]);
            float e2mn = fminf(e2p[ni].x, e2p[ni].y);
            if (xmin + e2mn - 2.f * mx < thr) {
                #pragma unroll
                for (int mi = 0; mi < 2; mi++)
                    #pragma unroll
                    for (int r = 0; r < 4; r++) {
                        float xv = x2v[mi * 2 + (r >> 1)];
                        float ev = (r & 1) ? e2p[ni].y : e2p[ni].x;
                        if (xv + ev - 2.f * acc[mi][ni][r] < thr) {
                            int row = bm + warpM * 32 + mi * 16 +
                                      (lane >> 2) + ((r >> 1) << 3);
                            int col = bn + warpN * 32 + ni * 8 +
                                      2 * (lane & 3) + (r & 1);
                            unsigned q = atomicAdd(&g_nsurv, 1u);
                            if (q < MAXSURV)
                                g_surv[q] = ((unsigned)row << 16) | (unsigned)col;
                        }
                    }
            }
        }
        __syncthreads();   // all reads of cur done before re-prefetch
    }
}

// ---------------------------------------------------------------------------
// Survivors: exact fp32 recompute + exp + scatter-add; last block finalizes
// logits = GAMMA * log(class_sims + EPS).
// ---------------------------------------------------------------------------
__global__ void survivor_finalize_kernel(const float* __restrict__ x,
                                         const float* __restrict__ ex,
                                         const int* __restrict__ labels,
                                         float* __restrict__ out,
                                         int B, int NE, int nout) {
    unsigned n = g_nsurv;
    if (n > MAXSURV) n = MAXSURV;
    const float beta = g_beta;
    for (unsigned i = blockIdx.x * blockDim.x + threadIdx.x; i < n;
         i += gridDim.x * blockDim.x) {
        unsigned p = g_surv[i];
        int row = (int)(p >> 16);
        int col = (int)(p & 0xFFFFu);
        if (row >= B || col >= NE) continue;
        const float* xr = x  + (size_t)row * DD;
        const float* er = ex + (size_t)col * DD;
        float s = 0.f;
        #pragma unroll
        for (int q = 0; q < DD / 4; q++) {
            float4 a = ((const float4*)xr)[q];
            float4 e = ((const float4*)er)[q];
            s += a.x*e.x + a.y*e.y + a.z*e.z + a.w*e.w;
        }
        float d2 = fmaxf(g_x2[row] + g_e2[col] - 2.f * s, 0.f);
        float bd = beta * d2;
        // skipped mass <= NE*exp(-60) << 1e-3 * EPS
        if (bd < 60.f)
            atomicAdd(&g_class[row * NUM_CLASSES + labels[col]], expf(-bd));
    }

    __shared__ unsigned s_last;
    __threadfence();
    __syncthreads();
    if (threadIdx.x == 0)
        s_last = (atomicAdd(&g_done, 1u) == gridDim.x - 1) ? 1u : 0u;
    __syncthreads();
    if (s_last) {
        __threadfence();
        for (int i = threadIdx.x; i < nout; i += blockDim.x)
            out[i] = GAMMA * logf(g_class[i] + EPS);
    }
}

// ---------------------------------------------------------------------------
extern "C" void kernel_launch(void* const* d_in, const int* in_sizes, int n_in,
                              void* d_out, int out_size) {
    const float* x        = (const float*)d_in[0];
    const float* ex       = (const float*)d_in[1];
    const int*   labels   = (const int*)d_in[2];
    const float* beta_raw = (const float*)d_in[3];
    float* out = (float*)d_out;

    const int B  = in_sizes[0] / DD;
    const int NE = in_sizes[1] / DD;

    const int prep_blocks = (NE_PAD + MAXB) / 32;   // 1596
    prep_kernel<<<prep_blocks, 256>>>(x, ex, beta_raw, B, NE);

    dim3 grid(GCOLS, (B + TM - 1) / TM);            // 74 x 8 = 592
    exemplar_mma_kernel<<<grid, 256>>>(B, NE);

    survivor_finalize_kernel<<<148, 256>>>(x, ex, labels, out, B, NE, out_size);
}